// round 1
// baseline (speedup 1.0000x reference)
#include <cuda_runtime.h>

// Problem constants
#define Bb   16
#define Nn   4096
#define Dd   1024
#define Hh   512
#define Cc   4
#define Ss   32                 // chunks per bag
#define ROWS (Nn / Ss)          // 128 rows per chunk
#define TPB  256
#define Gg   (Bb * Ss)          // 512 chunk-CTAs

// ---------------- scratch (static device allocations; no cudaMalloc) --------
__device__ float g_Pm[Gg];
__device__ float g_Pl[Gg];
__device__ float g_Pacc[Gg][Dd];
__device__ float g_Psum[Gg][Dd];
__device__ float g_Pmx[Gg][Dd];
__device__ float g_X[Bb][3 * Dd];
__device__ float g_Wc[3 * Dd][Cc];

// ---------------- pass 1: single-pass online-softmax pooling ----------------
// Each CTA: one (bag, chunk) of 128 rows. Thread t owns d-slots [4t, 4t+4).
// Per 4-row batch: coalesced float4 loads, block-reduced scores, then fold
// into running (m, l, acc) flash-style + mean/max accumulators. One read of
// bags total.
__global__ __launch_bounds__(TPB) void pass1_kernel(
    const float* __restrict__ bags, const float* __restrict__ query)
{
    const int g   = blockIdx.x;
    const int b   = g >> 5;          // g / Ss
    const int s   = g & (Ss - 1);
    const int tid = threadIdx.x;

    const float4 q = reinterpret_cast<const float4*>(query)[tid];

    __shared__ float sdots[4][8];

    float4 acc = make_float4(0.f, 0.f, 0.f, 0.f);
    float4 sum = make_float4(0.f, 0.f, 0.f, 0.f);
    float4 mxv = make_float4(-1e30f, -1e30f, -1e30f, -1e30f);
    float  m = -1e30f, l = 0.f;

    const long long rowbase = ((long long)b * Nn + (long long)s * ROWS);
    const float4* bp = reinterpret_cast<const float4*>(bags)
                     + rowbase * (Dd / 4) + tid;

    for (int r = 0; r < ROWS; r += 4) {
        // Batched loads: 4 independent float4s in flight per thread.
        float4 x0 = bp[(long long)(r + 0) * (Dd / 4)];
        float4 x1 = bp[(long long)(r + 1) * (Dd / 4)];
        float4 x2 = bp[(long long)(r + 2) * (Dd / 4)];
        float4 x3 = bp[(long long)(r + 3) * (Dd / 4)];

        float p0 = x0.x * q.x + x0.y * q.y + x0.z * q.z + x0.w * q.w;
        float p1 = x1.x * q.x + x1.y * q.y + x1.z * q.z + x1.w * q.w;
        float p2 = x2.x * q.x + x2.y * q.y + x2.z * q.z + x2.w * q.w;
        float p3 = x3.x * q.x + x3.y * q.y + x3.z * q.z + x3.w * q.w;

        #pragma unroll
        for (int o = 16; o > 0; o >>= 1) {
            p0 += __shfl_xor_sync(0xffffffffu, p0, o);
            p1 += __shfl_xor_sync(0xffffffffu, p1, o);
            p2 += __shfl_xor_sync(0xffffffffu, p2, o);
            p3 += __shfl_xor_sync(0xffffffffu, p3, o);
        }
        const int w = tid >> 5;
        if ((tid & 31) == 0) {
            sdots[0][w] = p0; sdots[1][w] = p1;
            sdots[2][w] = p2; sdots[3][w] = p3;
        }
        __syncthreads();
        float sc[4];
        #pragma unroll
        for (int rr = 0; rr < 4; rr++) {
            float t = 0.f;
            #pragma unroll
            for (int ww = 0; ww < 8; ww++) t += sdots[rr][ww];
            sc[rr] = t;                    // identical across all threads
        }
        __syncthreads();

        // Online softmax fold + mean/max, one row at a time.
#define MIL_UPDATE(X, SC)                                            \
        {                                                            \
            float mn   = fmaxf(m, (SC));                             \
            float corr = __expf(m - mn);                             \
            float p    = __expf((SC) - mn);                          \
            l = l * corr + p;                                        \
            acc.x = acc.x * corr + p * (X).x;                        \
            acc.y = acc.y * corr + p * (X).y;                        \
            acc.z = acc.z * corr + p * (X).z;                        \
            acc.w = acc.w * corr + p * (X).w;                        \
            sum.x += (X).x; sum.y += (X).y;                          \
            sum.z += (X).z; sum.w += (X).w;                          \
            mxv.x = fmaxf(mxv.x, (X).x); mxv.y = fmaxf(mxv.y, (X).y);\
            mxv.z = fmaxf(mxv.z, (X).z); mxv.w = fmaxf(mxv.w, (X).w);\
            m = mn;                                                  \
        }
        MIL_UPDATE(x0, sc[0])
        MIL_UPDATE(x1, sc[1])
        MIL_UPDATE(x2, sc[2])
        MIL_UPDATE(x3, sc[3])
#undef MIL_UPDATE
    }

    reinterpret_cast<float4*>(g_Pacc[g])[tid] = acc;
    reinterpret_cast<float4*>(g_Psum[g])[tid] = sum;
    reinterpret_cast<float4*>(g_Pmx[g])[tid]  = mxv;
    if (tid == 0) { g_Pm[g] = m; g_Pl[g] = l; }
}

// ---------------- pass 2: merge chunk partials per bag ----------------------
__global__ __launch_bounds__(TPB) void merge_kernel()
{
    const int b   = blockIdx.x;
    const int tid = threadIdx.x;

    float M = -1e30f;
    #pragma unroll
    for (int s = 0; s < Ss; s++) M = fmaxf(M, g_Pm[b * Ss + s]);

    float  L   = 0.f;
    float4 acc = make_float4(0.f, 0.f, 0.f, 0.f);
    float4 sum = make_float4(0.f, 0.f, 0.f, 0.f);
    float4 mxv = make_float4(-1e30f, -1e30f, -1e30f, -1e30f);

    for (int s = 0; s < Ss; s++) {
        const int g = b * Ss + s;
        const float w = __expf(g_Pm[g] - M);
        L += g_Pl[g] * w;
        float4 a = reinterpret_cast<const float4*>(g_Pacc[g])[tid];
        acc.x += a.x * w; acc.y += a.y * w; acc.z += a.z * w; acc.w += a.w * w;
        float4 u = reinterpret_cast<const float4*>(g_Psum[g])[tid];
        sum.x += u.x; sum.y += u.y; sum.z += u.z; sum.w += u.w;
        float4 v = reinterpret_cast<const float4*>(g_Pmx[g])[tid];
        mxv.x = fmaxf(mxv.x, v.x); mxv.y = fmaxf(mxv.y, v.y);
        mxv.z = fmaxf(mxv.z, v.z); mxv.w = fmaxf(mxv.w, v.w);
    }

    const float invN = 1.f / (float)Nn;
    const float invL = 1.f / L;
    float4 mean = make_float4(sum.x * invN, sum.y * invN, sum.z * invN, sum.w * invN);
    float4 attn = make_float4(acc.x * invL, acc.y * invL, acc.z * invL, acc.w * invL);

    reinterpret_cast<float4*>(&g_X[b][0])[tid]      = mean;
    reinterpret_cast<float4*>(&g_X[b][Dd])[tid]     = mxv;
    reinterpret_cast<float4*>(&g_X[b][2 * Dd])[tid] = attn;
}

// ---------------- Wc = W1 @ W2 (head is purely affine: no activation) -------
// One warp per output row d; W2 transposed into shared (conflict-free).
__global__ __launch_bounds__(TPB) void wc_kernel(
    const float* __restrict__ W1, const float* __restrict__ W2)
{
    __shared__ float sW2[Cc][Hh];
    const int tid = threadIdx.x;
    for (int i = tid; i < Hh * Cc; i += TPB) sW2[i & 3][i >> 2] = W2[i];
    __syncthreads();

    const int d    = blockIdx.x * 8 + (tid >> 5);
    const int lane = tid & 31;
    const float* row = W1 + (long long)d * Hh;

    float a0 = 0.f, a1 = 0.f, a2 = 0.f, a3 = 0.f;
    for (int j = lane; j < Hh; j += 32) {
        const float wv = row[j];
        a0 += wv * sW2[0][j]; a1 += wv * sW2[1][j];
        a2 += wv * sW2[2][j]; a3 += wv * sW2[3][j];
    }
    #pragma unroll
    for (int o = 16; o > 0; o >>= 1) {
        a0 += __shfl_xor_sync(0xffffffffu, a0, o);
        a1 += __shfl_xor_sync(0xffffffffu, a1, o);
        a2 += __shfl_xor_sync(0xffffffffu, a2, o);
        a3 += __shfl_xor_sync(0xffffffffu, a3, o);
    }
    if (lane == 0)
        reinterpret_cast<float4*>(g_Wc)[d] = make_float4(a0, a1, a2, a3);
}

// ---------------- final: out = x @ Wc + (b1 @ W2 + b2) ----------------------
__global__ __launch_bounds__(TPB) void out_kernel(
    const float* __restrict__ b1, const float* __restrict__ W2,
    const float* __restrict__ b2, float* __restrict__ out)
{
    const int b   = blockIdx.x;
    const int tid = threadIdx.x;

    float a0 = 0.f, a1 = 0.f, a2 = 0.f, a3 = 0.f;
    for (int d = tid; d < 3 * Dd; d += TPB) {
        const float  xv = g_X[b][d];
        const float4 wc = reinterpret_cast<const float4*>(g_Wc)[d];
        a0 += xv * wc.x; a1 += xv * wc.y; a2 += xv * wc.z; a3 += xv * wc.w;
    }
    for (int j = tid; j < Hh; j += TPB) {
        const float  bv = b1[j];
        const float4 w2 = reinterpret_cast<const float4*>(W2)[j];
        a0 += bv * w2.x; a1 += bv * w2.y; a2 += bv * w2.z; a3 += bv * w2.w;
    }
    #pragma unroll
    for (int o = 16; o > 0; o >>= 1) {
        a0 += __shfl_xor_sync(0xffffffffu, a0, o);
        a1 += __shfl_xor_sync(0xffffffffu, a1, o);
        a2 += __shfl_xor_sync(0xffffffffu, a2, o);
        a3 += __shfl_xor_sync(0xffffffffu, a3, o);
    }
    __shared__ float red[8][4];
    const int w = tid >> 5, lane = tid & 31;
    if (lane == 0) { red[w][0] = a0; red[w][1] = a1; red[w][2] = a2; red[w][3] = a3; }
    __syncthreads();
    if (tid < 4) {
        float t = b2[tid];
        #pragma unroll
        for (int ww = 0; ww < 8; ww++) t += red[ww][tid];
        out[b * 4 + tid] = t;
    }
}

// ---------------- launcher --------------------------------------------------
extern "C" void kernel_launch(void* const* d_in, const int* in_sizes, int n_in,
                              void* d_out, int out_size)
{
    const float* bags  = (const float*)d_in[0];   // [16, 4096, 1024]
    const float* query = (const float*)d_in[1];   // [1024]
    const float* W1    = (const float*)d_in[2];   // [3072, 512]
    const float* b1    = (const float*)d_in[3];   // [512]
    const float* W2    = (const float*)d_in[4];   // [512, 4]
    const float* b2    = (const float*)d_in[5];   // [4]
    float*       out   = (float*)d_out;           // [16, 4]

    pass1_kernel<<<Gg, TPB>>>(bags, query);
    merge_kernel<<<Bb, TPB>>>();
    wc_kernel<<<(3 * Dd) / 8, TPB>>>(W1, W2);
    out_kernel<<<Bb, TPB>>>(b1, W2, b2, out);
}

// round 2
// speedup vs baseline: 1.3192x; 1.3192x over previous
#include <cuda_runtime.h>

// Problem constants
#define Bb   16
#define Nn   4096
#define Dd   1024
#define Hh   512
#define Cc   4
#define Ss   32                 // chunks per bag
#define ROWS (Nn / Ss)          // 128 rows per chunk
#define TPB  256
#define Gg   (Bb * Ss)          // 512 pass1 CTAs
#define WCB  384                // Wc CTAs (8 W1-rows each)
#define BR   8                  // rows per batch in pass1

// ---------------- scratch (static device arrays; no cudaMalloc) -------------
__device__ float g_Pm[Gg];
__device__ float g_Pl[Gg];
__device__ float g_Pacc[Gg][Dd];
__device__ float g_Psum[Gg][Dd];
__device__ float g_Pmx[Gg][Dd];
__device__ float g_Wc[3 * Dd][Cc];   // W1 @ W2 (head is affine: no activation)

// ============================================================================
// K1: fused [pass1 online-softmax pooling] + [Wc = W1 @ W2]
//   blocks [0, Gg)        : one (bag, chunk) of 128 rows, single pass over bags
//   blocks [Gg, Gg+WCB)   : 8 rows of Wc each (overlaps with the streaming)
// ============================================================================
__global__ __launch_bounds__(TPB) void k1_kernel(
    const float* __restrict__ bags, const float* __restrict__ query,
    const float* __restrict__ W1,   const float* __restrict__ W2)
{
    const int blk = blockIdx.x;
    const int tid = threadIdx.x;

    if (blk < Gg) {
        // ---------------- pass1: thread t owns d-slots [4t, 4t+4) ----------
        const int b = blk >> 5;
        const int s = blk & (Ss - 1);

        __shared__ float sd[2][BR][8];     // [buf][row][warp] partial dots

        const float4 q = reinterpret_cast<const float4*>(query)[tid];

        float4 acc = make_float4(0.f, 0.f, 0.f, 0.f);
        float4 sum = make_float4(0.f, 0.f, 0.f, 0.f);
        float4 mxv = make_float4(-1e30f, -1e30f, -1e30f, -1e30f);
        float  m = -1e30f, l = 0.f;

        const long long rowbase = ((long long)b * Nn + (long long)s * ROWS);
        const float4* bp = reinterpret_cast<const float4*>(bags)
                         + rowbase * (Dd / 4) + tid;

        const int w    = tid >> 5;
        const int lane = tid & 31;
        int buf = 0;

        for (int r = 0; r < ROWS; r += BR) {
            // 8 independent float4 loads in flight (MLP_p1 = 8)
            float4 x[BR];
            #pragma unroll
            for (int i = 0; i < BR; i++)
                x[i] = bp[(long long)(r + i) * (Dd / 4)];

            // per-thread partial dots (independent chains)
            float p[BR];
            #pragma unroll
            for (int i = 0; i < BR; i++)
                p[i] = x[i].x * q.x + x[i].y * q.y + x[i].z * q.z + x[i].w * q.w;

            #pragma unroll
            for (int o = 16; o > 0; o >>= 1)
                #pragma unroll
                for (int i = 0; i < BR; i++)
                    p[i] += __shfl_xor_sync(0xffffffffu, p[i], o);

            if (lane == 0)
                #pragma unroll
                for (int i = 0; i < BR; i++) sd[buf][i][w] = p[i];
            __syncthreads();   // single barrier per batch (double-buffered sd)

            float sc[BR];
            #pragma unroll
            for (int i = 0; i < BR; i++) {
                float t = 0.f;
                #pragma unroll
                for (int ww = 0; ww < 8; ww++) t += sd[buf][i][ww];
                sc[i] = t;                       // identical across threads
            }
            buf ^= 1;

            // ---- batch-max online softmax: one rescale per 8 rows ----
            float bm = sc[0];
            #pragma unroll
            for (int i = 1; i < BR; i++) bm = fmaxf(bm, sc[i]);
            const float mn   = fmaxf(m, bm);
            const float corr = __expf(m - mn);
            float e[BR];
            #pragma unroll
            for (int i = 0; i < BR; i++) e[i] = __expf(sc[i] - mn);

            l *= corr;
            acc.x *= corr; acc.y *= corr; acc.z *= corr; acc.w *= corr;
            #pragma unroll
            for (int i = 0; i < BR; i++) {
                l += e[i];
                acc.x += e[i] * x[i].x; acc.y += e[i] * x[i].y;
                acc.z += e[i] * x[i].z; acc.w += e[i] * x[i].w;
                sum.x += x[i].x; sum.y += x[i].y;
                sum.z += x[i].z; sum.w += x[i].w;
                mxv.x = fmaxf(mxv.x, x[i].x); mxv.y = fmaxf(mxv.y, x[i].y);
                mxv.z = fmaxf(mxv.z, x[i].z); mxv.w = fmaxf(mxv.w, x[i].w);
            }
            m = mn;
        }

        reinterpret_cast<float4*>(g_Pacc[blk])[tid] = acc;
        reinterpret_cast<float4*>(g_Psum[blk])[tid] = sum;
        reinterpret_cast<float4*>(g_Pmx[blk])[tid]  = mxv;
        if (tid == 0) { g_Pm[blk] = m; g_Pl[blk] = l; }
    } else {
        // ---------------- Wc = W1 @ W2: one warp per W1 row -----------------
        __shared__ float sW2[Cc][Hh];
        for (int i = tid; i < Hh * Cc; i += TPB) sW2[i & 3][i >> 2] = W2[i];
        __syncthreads();

        const int d    = (blk - Gg) * 8 + (tid >> 5);
        const int lane = tid & 31;
        const float* row = W1 + (long long)d * Hh;

        float a0 = 0.f, a1 = 0.f, a2 = 0.f, a3 = 0.f;
        for (int j = lane; j < Hh; j += 32) {
            const float wv = row[j];
            a0 += wv * sW2[0][j]; a1 += wv * sW2[1][j];
            a2 += wv * sW2[2][j]; a3 += wv * sW2[3][j];
        }
        #pragma unroll
        for (int o = 16; o > 0; o >>= 1) {
            a0 += __shfl_xor_sync(0xffffffffu, a0, o);
            a1 += __shfl_xor_sync(0xffffffffu, a1, o);
            a2 += __shfl_xor_sync(0xffffffffu, a2, o);
            a3 += __shfl_xor_sync(0xffffffffu, a3, o);
        }
        if (lane == 0)
            reinterpret_cast<float4*>(g_Wc)[d] = make_float4(a0, a1, a2, a3);
    }
}

// ============================================================================
// K2: merge chunk partials AND compute out = X @ Wc + (b1 @ W2 + b2)
//   one block per bag, 768 threads; thread t owns float4 slot t of X[b]
//   (sec 0 = mean, 1 = max, 2 = attn). Fixed-order reductions: deterministic.
// ============================================================================
#define K2T 768
__global__ __launch_bounds__(K2T) void k2_kernel(
    const float* __restrict__ b1, const float* __restrict__ W2,
    const float* __restrict__ b2, float* __restrict__ out)
{
    const int b   = blockIdx.x;
    const int tid = threadIdx.x;
    const int sec = tid >> 8;          // 0: mean, 1: max, 2: attn
    const int d4  = tid & 255;
    const int g0  = b * Ss;

    // softmax merge constants (every thread; L1-broadcast loads, cheap)
    float pm[Ss];
    float M = -1e30f;
    #pragma unroll
    for (int s = 0; s < Ss; s++) { pm[s] = g_Pm[g0 + s]; M = fmaxf(M, pm[s]); }
    float L = 0.f;
    float we[Ss];
    #pragma unroll
    for (int s = 0; s < Ss; s++) { we[s] = __expf(pm[s] - M); L += g_Pl[g0 + s] * we[s]; }

    // merge this thread's X slot across 32 chunks
    float4 v;
    if (sec == 0) {
        float4 a = make_float4(0.f, 0.f, 0.f, 0.f);
        #pragma unroll
        for (int s = 0; s < Ss; s++) {
            float4 u = reinterpret_cast<const float4*>(g_Psum[g0 + s])[d4];
            a.x += u.x; a.y += u.y; a.z += u.z; a.w += u.w;
        }
        const float invN = 1.f / (float)Nn;
        v = make_float4(a.x * invN, a.y * invN, a.z * invN, a.w * invN);
    } else if (sec == 1) {
        float4 a = make_float4(-1e30f, -1e30f, -1e30f, -1e30f);
        #pragma unroll
        for (int s = 0; s < Ss; s++) {
            float4 u = reinterpret_cast<const float4*>(g_Pmx[g0 + s])[d4];
            a.x = fmaxf(a.x, u.x); a.y = fmaxf(a.y, u.y);
            a.z = fmaxf(a.z, u.z); a.w = fmaxf(a.w, u.w);
        }
        v = a;
    } else {
        float4 a = make_float4(0.f, 0.f, 0.f, 0.f);
        #pragma unroll
        for (int s = 0; s < Ss; s++) {
            float4 u = reinterpret_cast<const float4*>(g_Pacc[g0 + s])[d4];
            a.x += u.x * we[s]; a.y += u.y * we[s];
            a.z += u.z * we[s]; a.w += u.w * we[s];
        }
        const float invL = 1.f / L;
        v = make_float4(a.x * invL, a.y * invL, a.z * invL, a.w * invL);
    }

    // partial out contributions: 4 Wc rows for this thread's 4 d-slots
    const int   rbase = sec * Dd + d4 * 4;
    const float4 w0 = reinterpret_cast<const float4*>(g_Wc)[rbase + 0];
    const float4 w1 = reinterpret_cast<const float4*>(g_Wc)[rbase + 1];
    const float4 w2 = reinterpret_cast<const float4*>(g_Wc)[rbase + 2];
    const float4 w3 = reinterpret_cast<const float4*>(g_Wc)[rbase + 3];
    float o0 = v.x * w0.x + v.y * w1.x + v.z * w2.x + v.w * w3.x;
    float o1 = v.x * w0.y + v.y * w1.y + v.z * w2.y + v.w * w3.y;
    float o2 = v.x * w0.z + v.y * w1.z + v.z * w2.z + v.w * w3.z;
    float o3 = v.x * w0.w + v.y * w1.w + v.z * w2.w + v.w * w3.w;

    // bias term b1 @ W2 folded in once (threads 0..511, one j each)
    if (tid < Hh) {
        const float  bv = b1[tid];
        const float4 wr = reinterpret_cast<const float4*>(W2)[tid];
        o0 += bv * wr.x; o1 += bv * wr.y; o2 += bv * wr.z; o3 += bv * wr.w;
    }

    // block reduction (fixed order → deterministic)
    #pragma unroll
    for (int o = 16; o > 0; o >>= 1) {
        o0 += __shfl_xor_sync(0xffffffffu, o0, o);
        o1 += __shfl_xor_sync(0xffffffffu, o1, o);
        o2 += __shfl_xor_sync(0xffffffffu, o2, o);
        o3 += __shfl_xor_sync(0xffffffffu, o3, o);
    }
    __shared__ float red[24][4];
    const int w = tid >> 5, lane = tid & 31;
    if (lane == 0) { red[w][0] = o0; red[w][1] = o1; red[w][2] = o2; red[w][3] = o3; }
    __syncthreads();
    if (tid < 4) {
        float t = b2[tid];
        #pragma unroll
        for (int ww = 0; ww < 24; ww++) t += red[ww][tid];
        out[b * 4 + tid] = t;
    }
}

// ---------------- launcher --------------------------------------------------
extern "C" void kernel_launch(void* const* d_in, const int* in_sizes, int n_in,
                              void* d_out, int out_size)
{
    const float* bags  = (const float*)d_in[0];   // [16, 4096, 1024]
    const float* query = (const float*)d_in[1];   // [1024]
    const float* W1    = (const float*)d_in[2];   // [3072, 512]
    const float* b1    = (const float*)d_in[3];   // [512]
    const float* W2    = (const float*)d_in[4];   // [512, 4]
    const float* b2    = (const float*)d_in[5];   // [4]
    float*       out   = (float*)d_out;           // [16, 4]

    k1_kernel<<<Gg + WCB, TPB>>>(bags, query, W1, W2);
    k2_kernel<<<Bb, K2T>>>(b1, W2, b2, out);
}